// round 3
// baseline (speedup 1.0000x reference)
#include <cuda_runtime.h>
#include <stdint.h>

#define N_NODES 50000
#define D       128
#define EH      500000
#define ES      250000
#define NCLS    47

typedef unsigned long long ull;

// ---------------- scratch (device globals; no runtime allocation) ----------------
__device__ int   g_cnt[4 * N_NODES];
__device__ int   g_off[4 * (N_NODES + 1)];
__device__ int   g_cur[4 * N_NODES];
__device__ int   g_eidx[2 * (EH + ES)];        // src ids sorted by dst, per pair
__device__ float g_neigh[N_NODES * D];         // meanH + meanD (reused both layers)
__device__ float g_H1[N_NODES * D];            // layer-0 output

__device__ __forceinline__ int eidx_base(int p) {
    return p == 0 ? 0 : p == 1 ? EH : p == 2 ? (EH + ES) : (2 * EH + ES);
}

// ---------------- f32x2 packed math helpers ----------------
__device__ __forceinline__ ull fma2(ull a, ull b, ull c) {
    ull d;
    asm("fma.rn.f32x2 %0, %1, %2, %3;" : "=l"(d) : "l"(a), "l"(b), "l"(c));
    return d;
}
__device__ __forceinline__ ull packf2(float x, float y) {
    ull d;
    asm("mov.b64 %0, {%1, %2};" : "=l"(d) : "f"(x), "f"(y));
    return d;
}
__device__ __forceinline__ void unpackf2(ull v, float& x, float& y) {
    asm("mov.b64 {%0, %1}, %2;" : "=f"(x), "=f"(y) : "l"(v));
}

// ---------------- CSR build ----------------
__global__ void zero_cnt_kernel() {
    int i = blockIdx.x * blockDim.x + threadIdx.x;
    if (i < 4 * N_NODES) g_cnt[i] = 0;
}

__global__ void count_kernel(const int* __restrict__ dst, int n, int pair) {
    int i = blockIdx.x * blockDim.x + threadIdx.x;
    if (i < n) atomicAdd(&g_cnt[pair * N_NODES + __ldg(dst + i)], 1);
}

// 4 blocks (one per pair), 1024 threads; serial-chunk + block scan
__global__ void scan_kernel() {
    const int p = blockIdx.x;
    int* cnt = g_cnt + p * N_NODES;
    int* off = g_off + p * (N_NODES + 1);
    int* cur = g_cur + p * N_NODES;
    const int T = 1024;
    const int C = (N_NODES + T - 1) / T;   // 49
    __shared__ int part[T];
    int t = threadIdx.x;
    int base = t * C;
    int s = 0;
#pragma unroll 1
    for (int i = 0; i < C; i++) {
        int j = base + i;
        if (j < N_NODES) s += cnt[j];
    }
    part[t] = s;
    __syncthreads();
    for (int d2 = 1; d2 < T; d2 <<= 1) {
        int v = (t >= d2) ? part[t - d2] : 0;
        __syncthreads();
        part[t] += v;
        __syncthreads();
    }
    int run = part[t] - s;   // exclusive prefix for this thread's chunk
#pragma unroll 1
    for (int i = 0; i < C; i++) {
        int j = base + i;
        if (j < N_NODES) {
            off[j] = run;
            cur[j] = run;
            run += cnt[j];
        }
    }
    if (t == T - 1) off[N_NODES] = part[t];
}

__global__ void bucket_kernel(const int* __restrict__ src,
                              const int* __restrict__ dst, int n, int pair) {
    int i = blockIdx.x * blockDim.x + threadIdx.x;
    if (i < n) {
        int d = __ldg(dst + i);
        int pos = atomicAdd(&g_cur[pair * N_NODES + d], 1);
        g_eidx[eidx_base(pair) + pos] = __ldg(src + i);
    }
}

// ---------------- gather aggregation (warp per dst node) ----------------
// hist: g_neigh[d] = mean_{e in in(d)} hbar[src(e)]
template <int PAIR>
__global__ void agg_hist_kernel(const float* __restrict__ feat) {
    int g = blockIdx.x * blockDim.x + threadIdx.x;
    int w = g >> 5, lane = g & 31;
    if (w >= N_NODES) return;
    const int* off = g_off + PAIR * (N_NODES + 1);
    const int* idx = g_eidx + eidx_base(PAIR);
    int s0 = __ldg(off + w), s1 = __ldg(off + w + 1);
    float4 acc = make_float4(0.f, 0.f, 0.f, 0.f);
#pragma unroll 2
    for (int e = s0; e < s1; e++) {
        int s = __ldg(idx + e);
        float4 v = __ldg((const float4*)(feat + (size_t)s * D) + lane);
        acc.x += v.x; acc.y += v.y; acc.z += v.z; acc.w += v.w;
    }
    float inv = 1.f / fmaxf((float)(s1 - s0), 1.f);
    float4 o = make_float4(acc.x * inv, acc.y * inv, acc.z * inv, acc.w * inv);
    *(float4*)(g_neigh + (size_t)w * D + lane * 4) = o;
}

// delta: g_neigh[d] += mean_{e} (H[src] - HBar[src])
template <int PAIR, int LAYER>
__global__ void agg_delta_kernel(const float* __restrict__ Hext,
                                 const float* __restrict__ hbar) {
    int g = blockIdx.x * blockDim.x + threadIdx.x;
    int w = g >> 5, lane = g & 31;
    if (w >= N_NODES) return;
    const float* H = (LAYER == 0) ? Hext : g_H1;
    const int* off = g_off + PAIR * (N_NODES + 1);
    const int* idx = g_eidx + eidx_base(PAIR);
    int s0 = __ldg(off + w), s1 = __ldg(off + w + 1);
    if (s0 == s1) return;                      // nothing to add
    float4 acc = make_float4(0.f, 0.f, 0.f, 0.f);
#pragma unroll 2
    for (int e = s0; e < s1; e++) {
        int s = __ldg(idx + e);
        float4 a = __ldg((const float4*)(H    + (size_t)s * D) + lane);
        float4 b = __ldg((const float4*)(hbar + (size_t)s * D) + lane);
        acc.x += a.x - b.x; acc.y += a.y - b.y;
        acc.z += a.z - b.z; acc.w += a.w - b.w;
    }
    float inv = 1.f / (float)(s1 - s0);
    float4* dst = (float4*)(g_neigh + (size_t)w * D + lane * 4);
    float4 o = *dst;
    o.x += acc.x * inv; o.y += acc.y * inv;
    o.z += acc.z * inv; o.w += acc.w * inv;
    *dst = o;
}

// ---------------- GEMM + bias + ReLU ----------------
// out[r][n] = relu(b[n] + sum_k z[r][k] W[n][k]),  z = [H_row | g_neigh_row]
// BM=64 x BN, BK=32, 256 threads, TM=4 x TN=BN/16, f32x2 packed FMA,
// swizzled transposed smem tiles (conflict-free STS + LDS.128 fragments).
template <int LAYER, int DOUT, int BN>
__global__ void __launch_bounds__(256, 3)
gemm_kernel(const float* __restrict__ Hext,
            const float* __restrict__ W,
            const float* __restrict__ bias,
            float* __restrict__ outext) {
    constexpr int BM = 64, BK = 32, K = 2 * D;
    constexpr int TM = 4;
    constexpr int TN = BN / 16;
    constexpr int TNP = TN / 2;
    constexpr int APAD = BM + 4;
    constexpr int BPAD = BN + 4;

    const float* H = (LAYER == 0) ? Hext : g_H1;
    float* out     = (LAYER == 0) ? g_H1 : outext;

    __shared__ float As[BK][APAD];
    __shared__ float Bs[BK][BPAD];

    const int t    = threadIdx.x;
    const int row0 = blockIdx.x * BM;
    const int tx   = t & 15;
    const int ty   = t >> 4;

    ull acc2[TM][TNP];
#pragma unroll
    for (int i = 0; i < TM; i++)
#pragma unroll
        for (int p = 0; p < TNP; p++) acc2[i][p] = 0ULL;

    for (int kit = 0; kit < K / BK; kit++) {
        const int k0 = kit * BK;
        const float* Asrc = (k0 < D) ? (H + k0) : (g_neigh + (k0 - D));
        __syncthreads();

        // A tile: 64x32, 2 float4/thread, transposed+swizzled store
#pragma unroll
        for (int v = 0; v < (BM * BK) / (256 * 4); v++) {
            int id = v * 256 + t;
            int m  = id >> 3;
            int kq = id & 7;
            int r  = min(row0 + m, N_NODES - 1);
            float4 val = __ldg((const float4*)(Asrc + (size_t)r * D) + kq);
            int col = (((m >> 2) ^ (kq >> 1)) << 2) + (m & 3);
            As[(kq << 2) + 0][col] = val.x;
            As[(kq << 2) + 1][col] = val.y;
            As[(kq << 2) + 2][col] = val.z;
            As[(kq << 2) + 3][col] = val.w;
        }
        // B tile
#pragma unroll
        for (int v = 0; v < (BN * BK) / (256 * 4); v++) {
            int id = v * 256 + t;
            int n  = id >> 3;
            int kq = id & 7;
            float4 w = make_float4(0.f, 0.f, 0.f, 0.f);
            if (n < DOUT) w = __ldg((const float4*)(W + n * K + k0) + kq);
            int col = (((n >> 2) ^ (kq >> 1)) << 2) + (n & 3);
            Bs[(kq << 2) + 0][col] = w.x;
            Bs[(kq << 2) + 1][col] = w.y;
            Bs[(kq << 2) + 2][col] = w.z;
            Bs[(kq << 2) + 3][col] = w.w;
        }
        __syncthreads();

#pragma unroll
        for (int kk = 0; kk < BK; kk++) {
            const int s = (kk >> 3) & 3;
            float4 a = *(const float4*)&As[kk][((ty ^ s) & 15) << 2];
            ull ad[TM];
            ad[0] = packf2(a.x, a.x); ad[1] = packf2(a.y, a.y);
            ad[2] = packf2(a.z, a.z); ad[3] = packf2(a.w, a.w);
            ull bp[TNP];
#pragma unroll
            for (int u = 0; u < TN / 4; u++) {
                int gidx = (tx * (TN / 4) + u) ^ s;
                float4 b = *(const float4*)&Bs[kk][gidx << 2];
                bp[2 * u + 0] = packf2(b.x, b.y);
                bp[2 * u + 1] = packf2(b.z, b.w);
            }
#pragma unroll
            for (int i = 0; i < TM; i++)
#pragma unroll
                for (int p = 0; p < TNP; p++)
                    acc2[i][p] = fma2(ad[i], bp[p], acc2[i][p]);
        }
    }

    // epilogue
    float bn[TN];
#pragma unroll
    for (int j = 0; j < TN; j++) {
        int n = tx * TN + j;
        bn[j] = (n < DOUT) ? __ldg(bias + n) : 0.f;
    }
#pragma unroll
    for (int i = 0; i < TM; i++) {
        int r = row0 + ty * TM + i;
        if (r >= N_NODES) continue;
        float res[TN];
#pragma unroll
        for (int p = 0; p < TNP; p++) {
            float lo, hi;
            unpackf2(acc2[i][p], lo, hi);
            res[2 * p + 0] = fmaxf(lo + bn[2 * p + 0], 0.f);
            res[2 * p + 1] = fmaxf(hi + bn[2 * p + 1], 0.f);
        }
        if (DOUT == BN) {
#pragma unroll
            for (int u = 0; u < TN / 4; u++) {
                float4 o = make_float4(res[4 * u], res[4 * u + 1],
                                       res[4 * u + 2], res[4 * u + 3]);
                *(float4*)(out + (size_t)r * DOUT + tx * TN + 4 * u) = o;
            }
        } else {
#pragma unroll
            for (int j = 0; j < TN; j++) {
                int n = tx * TN + j;
                if (n < DOUT) out[(size_t)r * DOUT + n] = res[j];
            }
        }
    }
}

// ---------------- launch ----------------
extern "C" void kernel_launch(void* const* d_in, const int* in_sizes, int n_in,
                              void* d_out, int out_size) {
    const float* x     = (const float*)d_in[0];
    const float* hbar0 = (const float*)d_in[1];
    const float* hbar1 = (const float*)d_in[2];
    const float* W0    = (const float*)d_in[3];
    const float* b0    = (const float*)d_in[4];
    const float* W1    = (const float*)d_in[5];
    const float* b1    = (const float*)d_in[6];
    const int* hsrc0   = (const int*)d_in[7];
    const int* hdst0   = (const int*)d_in[8];
    const int* ssrc0   = (const int*)d_in[9];
    const int* sdst0   = (const int*)d_in[10];
    const int* hsrc1   = (const int*)d_in[11];
    const int* hdst1   = (const int*)d_in[12];
    const int* ssrc1   = (const int*)d_in[13];
    const int* sdst1   = (const int*)d_in[14];
    float* out = (float*)d_out;

    const int GE_H = (EH + 255) / 256;           // 1954
    const int GE_S = (ES + 255) / 256;           // 977
    const int GAGG = (N_NODES * 32 + 255) / 256; // 6250
    const int GL   = (N_NODES + 63) / 64;        // 782

    // ---- CSR build (all 4 pairs) ----
    zero_cnt_kernel<<<(4 * N_NODES + 255) / 256, 256>>>();
    count_kernel<<<GE_H, 256>>>(hdst0, EH, 0);
    count_kernel<<<GE_S, 256>>>(sdst0, ES, 1);
    count_kernel<<<GE_H, 256>>>(hdst1, EH, 2);
    count_kernel<<<GE_S, 256>>>(sdst1, ES, 3);
    scan_kernel<<<4, 1024>>>();
    bucket_kernel<<<GE_H, 256>>>(hsrc0, hdst0, EH, 0);
    bucket_kernel<<<GE_S, 256>>>(ssrc0, sdst0, ES, 1);
    bucket_kernel<<<GE_H, 256>>>(hsrc1, hdst1, EH, 2);
    bucket_kernel<<<GE_S, 256>>>(ssrc1, sdst1, ES, 3);

    // ---- layer 0 ----
    agg_hist_kernel<0><<<GAGG, 256>>>(hbar0);
    agg_delta_kernel<1, 0><<<GAGG, 256>>>(x, hbar0);
    gemm_kernel<0, 128, 128><<<GL, 256>>>(x, W0, b0, nullptr);

    // ---- layer 1 ----
    agg_hist_kernel<2><<<GAGG, 256>>>(hbar1);
    agg_delta_kernel<3, 1><<<GAGG, 256>>>(nullptr, hbar1);
    gemm_kernel<1, NCLS, 64><<<GL, 256>>>(nullptr, W1, b1, out);
}

// round 4
// speedup vs baseline: 1.0832x; 1.0832x over previous
#include <cuda_runtime.h>
#include <stdint.h>

#define N_NODES 50000
#define D       128
#define EH      500000
#define ES      250000
#define NCLS    47
#define E_TOT   (2 * (EH + ES))

typedef unsigned long long ull;

// ---------------- scratch (device globals; no runtime allocation) ----------------
__device__ int   g_cnt[4 * N_NODES];
__device__ int   g_off[4 * (N_NODES + 1)];
__device__ int   g_cur[4 * N_NODES];
__device__ int   g_eidx[E_TOT];                // src ids grouped by dst, per pair
__device__ float g_neigh[N_NODES * D];         // meanH + meanD (reused both layers)
__device__ float g_H1[N_NODES * D];            // layer-0 output
__device__ float g_Hd[N_NODES * D];            // H - HBar (reused both layers)

__device__ __forceinline__ int eidx_base(int p) {
    return p == 0 ? 0 : p == 1 ? EH : p == 2 ? (EH + ES) : (2 * EH + ES);
}

// ---------------- f32x2 packed math helpers ----------------
__device__ __forceinline__ ull fma2(ull a, ull b, ull c) {
    ull d;
    asm("fma.rn.f32x2 %0, %1, %2, %3;" : "=l"(d) : "l"(a), "l"(b), "l"(c));
    return d;
}
__device__ __forceinline__ ull packf2(float x, float y) {
    ull d;
    asm("mov.b64 %0, {%1, %2};" : "=l"(d) : "f"(x), "f"(y));
    return d;
}
__device__ __forceinline__ void unpackf2(ull v, float& x, float& y) {
    asm("mov.b64 {%0, %1}, %2;" : "=f"(x), "=f"(y) : "l"(v));
}

// ---------------- CSR build (fused) ----------------
__global__ void count_all_kernel(const int* __restrict__ hd0, const int* __restrict__ sd0,
                                 const int* __restrict__ hd1, const int* __restrict__ sd1) {
    int i = blockIdx.x * blockDim.x + threadIdx.x;
    if (i >= E_TOT) return;
    int pair, off;
    const int* p;
    if (i < EH)                 { pair = 0; p = hd0; off = i; }
    else if (i < EH + ES)       { pair = 1; p = sd0; off = i - EH; }
    else if (i < 2 * EH + ES)   { pair = 2; p = hd1; off = i - EH - ES; }
    else                        { pair = 3; p = sd1; off = i - 2 * EH - ES; }
    atomicAdd(&g_cnt[pair * N_NODES + __ldg(p + off)], 1);
}

// 4 blocks (one per pair), 1024 threads; serial-chunk + block scan
__global__ void scan_kernel() {
    const int p = blockIdx.x;
    int* cnt = g_cnt + p * N_NODES;
    int* off = g_off + p * (N_NODES + 1);
    int* cur = g_cur + p * N_NODES;
    const int T = 1024;
    const int C = (N_NODES + T - 1) / T;   // 49
    __shared__ int part[T];
    int t = threadIdx.x;
    int base = t * C;
    int s = 0;
#pragma unroll 1
    for (int i = 0; i < C; i++) {
        int j = base + i;
        if (j < N_NODES) s += cnt[j];
    }
    part[t] = s;
    __syncthreads();
    for (int d2 = 1; d2 < T; d2 <<= 1) {
        int v = (t >= d2) ? part[t - d2] : 0;
        __syncthreads();
        part[t] += v;
        __syncthreads();
    }
    int run = part[t] - s;
#pragma unroll 1
    for (int i = 0; i < C; i++) {
        int j = base + i;
        if (j < N_NODES) {
            off[j] = run;
            cur[j] = run;
            run += cnt[j];
        }
    }
    if (t == T - 1) off[N_NODES] = part[t];
}

__global__ void bucket_all_kernel(const int* __restrict__ hs0, const int* __restrict__ hd0,
                                  const int* __restrict__ ss0, const int* __restrict__ sd0,
                                  const int* __restrict__ hs1, const int* __restrict__ hd1,
                                  const int* __restrict__ ss1, const int* __restrict__ sd1) {
    int i = blockIdx.x * blockDim.x + threadIdx.x;
    if (i >= E_TOT) return;
    int pair, off;
    const int *ps, *pd;
    if (i < EH)                 { pair = 0; ps = hs0; pd = hd0; off = i; }
    else if (i < EH + ES)       { pair = 1; ps = ss0; pd = sd0; off = i - EH; }
    else if (i < 2 * EH + ES)   { pair = 2; ps = hs1; pd = hd1; off = i - EH - ES; }
    else                        { pair = 3; ps = ss1; pd = sd1; off = i - 2 * EH - ES; }
    int d = __ldg(pd + off);
    int pos = atomicAdd(&g_cur[pair * N_NODES + d], 1);
    g_eidx[eidx_base(pair) + pos] = __ldg(ps + off);
}

// ---------------- Hdelta = H - HBar (coalesced elementwise) ----------------
// LAYER 0: H = external x; LAYER 1: H = g_H1
template <int LAYER>
__global__ void hdelta_kernel(const float* __restrict__ Hext, const float* __restrict__ hbar) {
    int i = blockIdx.x * blockDim.x + threadIdx.x;
    if (i >= N_NODES * D / 4) return;
    const float4* H4 = (LAYER == 0) ? (const float4*)Hext : (const float4*)g_H1;
    float4 a = __ldg(H4 + i);
    float4 b = __ldg((const float4*)hbar + i);
    ((float4*)g_Hd)[i] = make_float4(a.x - b.x, a.y - b.y, a.z - b.z, a.w - b.w);
}

// ---------------- fused gather aggregation (warp per dst node) ----------------
// g_neigh[w] = mean_{hist in(w)} hbar[src] + mean_{samp in(w)} g_Hd[src]
template <int HPAIR, int DPAIR>
__global__ void agg_fused_kernel(const float* __restrict__ hbar) {
    int g = blockIdx.x * blockDim.x + threadIdx.x;
    int w = g >> 5, lane = g & 31;
    if (w >= N_NODES) return;
    const int* offH = g_off + HPAIR * (N_NODES + 1);
    const int* offD = g_off + DPAIR * (N_NODES + 1);
    const int* idxH = g_eidx + eidx_base(HPAIR);
    const int* idxD = g_eidx + eidx_base(DPAIR);
    int h0 = __ldg(offH + w), h1 = __ldg(offH + w + 1);
    int d0 = __ldg(offD + w), d1 = __ldg(offD + w + 1);

    float4 acc = make_float4(0.f, 0.f, 0.f, 0.f);
#pragma unroll 2
    for (int e = h0; e < h1; e++) {
        int s = __ldg(idxH + e);
        float4 v = __ldg((const float4*)(hbar + (size_t)s * D) + lane);
        acc.x += v.x; acc.y += v.y; acc.z += v.z; acc.w += v.w;
    }
    float invh = 1.f / fmaxf((float)(h1 - h0), 1.f);
    float4 o = make_float4(acc.x * invh, acc.y * invh, acc.z * invh, acc.w * invh);

    float4 accd = make_float4(0.f, 0.f, 0.f, 0.f);
#pragma unroll 2
    for (int e = d0; e < d1; e++) {
        int s = __ldg(idxD + e);
        float4 v = __ldg((const float4*)(g_Hd + (size_t)s * D) + lane);
        accd.x += v.x; accd.y += v.y; accd.z += v.z; accd.w += v.w;
    }
    float invd = 1.f / fmaxf((float)(d1 - d0), 1.f);
    o.x += accd.x * invd; o.y += accd.y * invd;
    o.z += accd.z * invd; o.w += accd.w * invd;

    *(float4*)(g_neigh + (size_t)w * D + lane * 4) = o;
}

// ---------------- GEMM + bias + ReLU ----------------
template <int LAYER, int DOUT, int BN>
__global__ void __launch_bounds__(256, 3)
gemm_kernel(const float* __restrict__ Hext,
            const float* __restrict__ W,
            const float* __restrict__ bias,
            float* __restrict__ outext) {
    constexpr int BM = 64, BK = 32, K = 2 * D;
    constexpr int TM = 4;
    constexpr int TN = BN / 16;
    constexpr int TNP = TN / 2;
    constexpr int APAD = BM + 4;
    constexpr int BPAD = BN + 4;

    const float* H = (LAYER == 0) ? Hext : g_H1;
    float* out     = (LAYER == 0) ? g_H1 : outext;

    __shared__ float As[BK][APAD];
    __shared__ float Bs[BK][BPAD];

    const int t    = threadIdx.x;
    const int row0 = blockIdx.x * BM;
    const int tx   = t & 15;
    const int ty   = t >> 4;

    ull acc2[TM][TNP];
#pragma unroll
    for (int i = 0; i < TM; i++)
#pragma unroll
        for (int p = 0; p < TNP; p++) acc2[i][p] = 0ULL;

    for (int kit = 0; kit < K / BK; kit++) {
        const int k0 = kit * BK;
        const float* Asrc = (k0 < D) ? (H + k0) : (g_neigh + (k0 - D));
        __syncthreads();

#pragma unroll
        for (int v = 0; v < (BM * BK) / (256 * 4); v++) {
            int id = v * 256 + t;
            int m  = id >> 3;
            int kq = id & 7;
            int r  = min(row0 + m, N_NODES - 1);
            float4 val = __ldg((const float4*)(Asrc + (size_t)r * D) + kq);
            int col = (((m >> 2) ^ (kq >> 1)) << 2) + (m & 3);
            As[(kq << 2) + 0][col] = val.x;
            As[(kq << 2) + 1][col] = val.y;
            As[(kq << 2) + 2][col] = val.z;
            As[(kq << 2) + 3][col] = val.w;
        }
#pragma unroll
        for (int v = 0; v < (BN * BK) / (256 * 4); v++) {
            int id = v * 256 + t;
            int n  = id >> 3;
            int kq = id & 7;
            float4 w = make_float4(0.f, 0.f, 0.f, 0.f);
            if (n < DOUT) w = __ldg((const float4*)(W + n * K + k0) + kq);
            int col = (((n >> 2) ^ (kq >> 1)) << 2) + (n & 3);
            Bs[(kq << 2) + 0][col] = w.x;
            Bs[(kq << 2) + 1][col] = w.y;
            Bs[(kq << 2) + 2][col] = w.z;
            Bs[(kq << 2) + 3][col] = w.w;
        }
        __syncthreads();

#pragma unroll
        for (int kk = 0; kk < BK; kk++) {
            const int s = (kk >> 3) & 3;
            float4 a = *(const float4*)&As[kk][((ty ^ s) & 15) << 2];
            ull ad[TM];
            ad[0] = packf2(a.x, a.x); ad[1] = packf2(a.y, a.y);
            ad[2] = packf2(a.z, a.z); ad[3] = packf2(a.w, a.w);
            ull bp[TNP];
#pragma unroll
            for (int u = 0; u < TN / 4; u++) {
                int gidx = (tx * (TN / 4) + u) ^ s;
                float4 b = *(const float4*)&Bs[kk][gidx << 2];
                bp[2 * u + 0] = packf2(b.x, b.y);
                bp[2 * u + 1] = packf2(b.z, b.w);
            }
#pragma unroll
            for (int i = 0; i < TM; i++)
#pragma unroll
                for (int p = 0; p < TNP; p++)
                    acc2[i][p] = fma2(ad[i], bp[p], acc2[i][p]);
        }
    }

    float bn[TN];
#pragma unroll
    for (int j = 0; j < TN; j++) {
        int n = tx * TN + j;
        bn[j] = (n < DOUT) ? __ldg(bias + n) : 0.f;
    }
#pragma unroll
    for (int i = 0; i < TM; i++) {
        int r = row0 + ty * TM + i;
        if (r >= N_NODES) continue;
        float res[TN];
#pragma unroll
        for (int p = 0; p < TNP; p++) {
            float lo, hi;
            unpackf2(acc2[i][p], lo, hi);
            res[2 * p + 0] = fmaxf(lo + bn[2 * p + 0], 0.f);
            res[2 * p + 1] = fmaxf(hi + bn[2 * p + 1], 0.f);
        }
        if (DOUT == BN) {
#pragma unroll
            for (int u = 0; u < TN / 4; u++) {
                float4 o = make_float4(res[4 * u], res[4 * u + 1],
                                       res[4 * u + 2], res[4 * u + 3]);
                *(float4*)(out + (size_t)r * DOUT + tx * TN + 4 * u) = o;
            }
        } else {
#pragma unroll
            for (int j = 0; j < TN; j++) {
                int n = tx * TN + j;
                if (n < DOUT) out[(size_t)r * DOUT + n] = res[j];
            }
        }
    }
}

// ---------------- launch ----------------
extern "C" void kernel_launch(void* const* d_in, const int* in_sizes, int n_in,
                              void* d_out, int out_size) {
    const float* x     = (const float*)d_in[0];
    const float* hbar0 = (const float*)d_in[1];
    const float* hbar1 = (const float*)d_in[2];
    const float* W0    = (const float*)d_in[3];
    const float* b0    = (const float*)d_in[4];
    const float* W1    = (const float*)d_in[5];
    const float* b1    = (const float*)d_in[6];
    const int* hsrc0   = (const int*)d_in[7];
    const int* hdst0   = (const int*)d_in[8];
    const int* ssrc0   = (const int*)d_in[9];
    const int* sdst0   = (const int*)d_in[10];
    const int* hsrc1   = (const int*)d_in[11];
    const int* hdst1   = (const int*)d_in[12];
    const int* ssrc1   = (const int*)d_in[13];
    const int* sdst1   = (const int*)d_in[14];
    float* out = (float*)d_out;

    const int GE   = (E_TOT + 255) / 256;         // 5860
    const int GAGG = (N_NODES * 32 + 255) / 256;  // 6250
    const int GEL  = (N_NODES * D / 4 + 255) / 256;
    const int GL   = (N_NODES + 63) / 64;         // 782

    // ---- CSR build ----
    void* cnt_ptr = nullptr;
    cudaGetSymbolAddress(&cnt_ptr, g_cnt);
    cudaMemsetAsync(cnt_ptr, 0, sizeof(int) * 4 * N_NODES);
    count_all_kernel<<<GE, 256>>>(hdst0, sdst0, hdst1, sdst1);
    scan_kernel<<<4, 1024>>>();
    bucket_all_kernel<<<GE, 256>>>(hsrc0, hdst0, ssrc0, sdst0,
                                   hsrc1, hdst1, ssrc1, sdst1);

    // ---- layer 0 ----
    hdelta_kernel<0><<<GEL, 256>>>(x, hbar0);
    agg_fused_kernel<0, 1><<<GAGG, 256>>>(hbar0);
    gemm_kernel<0, 128, 128><<<GL, 256>>>(x, W0, b0, nullptr);

    // ---- layer 1 ----
    hdelta_kernel<1><<<GEL, 256>>>(nullptr, hbar1);
    agg_fused_kernel<2, 3><<<GAGG, 256>>>(hbar1);
    gemm_kernel<1, NCLS, 64><<<GL, 256>>>(nullptr, W1, b1, out);
}

// round 5
// speedup vs baseline: 1.1437x; 1.0559x over previous
#include <cuda_runtime.h>
#include <stdint.h>

#define N_NODES 50000
#define D       128
#define EH      500000
#define ES      250000
#define NCLS    47
#define E_TOT   (2 * (EH + ES))

typedef unsigned long long ull;

// ---------------- scratch (device globals; no runtime allocation) ----------------
__device__ int   g_cnt[4 * N_NODES];
__device__ int   g_off[4 * (N_NODES + 1)];
__device__ int   g_cur[4 * N_NODES];
__device__ int   g_eidx[E_TOT];                // src ids grouped by dst, per pair
__device__ float g_neigh[N_NODES * D];         // meanH + meanD (reused both layers)
__device__ float g_H1[N_NODES * D];            // layer-0 output
__device__ float g_Hd[N_NODES * D];            // H - HBar (reused both layers)

__device__ __forceinline__ int eidx_base(int p) {
    return p == 0 ? 0 : p == 1 ? EH : p == 2 ? (EH + ES) : (2 * EH + ES);
}

// ---------------- f32x2 packed math helpers ----------------
__device__ __forceinline__ ull fma2(ull a, ull b, ull c) {
    ull d;
    asm("fma.rn.f32x2 %0, %1, %2, %3;" : "=l"(d) : "l"(a), "l"(b), "l"(c));
    return d;
}
__device__ __forceinline__ ull packf2(float x, float y) {
    ull d;
    asm("mov.b64 %0, {%1, %2};" : "=l"(d) : "f"(x), "f"(y));
    return d;
}
__device__ __forceinline__ void unpackf2(ull v, float& x, float& y) {
    asm("mov.b64 {%0, %1}, %2;" : "=f"(x), "=f"(y) : "l"(v));
}

// ---------------- CSR build (fused) ----------------
__global__ void count_all_kernel(const int* __restrict__ hd0, const int* __restrict__ sd0,
                                 const int* __restrict__ hd1, const int* __restrict__ sd1) {
    int i = blockIdx.x * blockDim.x + threadIdx.x;
    if (i >= E_TOT) return;
    int pair, off;
    const int* p;
    if (i < EH)                 { pair = 0; p = hd0; off = i; }
    else if (i < EH + ES)       { pair = 1; p = sd0; off = i - EH; }
    else if (i < 2 * EH + ES)   { pair = 2; p = hd1; off = i - EH - ES; }
    else                        { pair = 3; p = sd1; off = i - 2 * EH - ES; }
    atomicAdd(&g_cnt[pair * N_NODES + __ldg(p + off)], 1);
}

// 4 blocks (one per pair), 1024 threads; serial-chunk + block scan
__global__ void scan_kernel() {
    const int p = blockIdx.x;
    int* cnt = g_cnt + p * N_NODES;
    int* off = g_off + p * (N_NODES + 1);
    int* cur = g_cur + p * N_NODES;
    const int T = 1024;
    const int C = (N_NODES + T - 1) / T;   // 49
    __shared__ int part[T];
    int t = threadIdx.x;
    int base = t * C;
    int s = 0;
#pragma unroll 1
    for (int i = 0; i < C; i++) {
        int j = base + i;
        if (j < N_NODES) s += cnt[j];
    }
    part[t] = s;
    __syncthreads();
    for (int d2 = 1; d2 < T; d2 <<= 1) {
        int v = (t >= d2) ? part[t - d2] : 0;
        __syncthreads();
        part[t] += v;
        __syncthreads();
    }
    int run = part[t] - s;
#pragma unroll 1
    for (int i = 0; i < C; i++) {
        int j = base + i;
        if (j < N_NODES) {
            off[j] = run;
            cur[j] = run;
            run += cnt[j];
        }
    }
    if (t == T - 1) off[N_NODES] = part[t];
}

__global__ void bucket_all_kernel(const int* __restrict__ hs0, const int* __restrict__ hd0,
                                  const int* __restrict__ ss0, const int* __restrict__ sd0,
                                  const int* __restrict__ hs1, const int* __restrict__ hd1,
                                  const int* __restrict__ ss1, const int* __restrict__ sd1) {
    int i = blockIdx.x * blockDim.x + threadIdx.x;
    if (i >= E_TOT) return;
    int pair, off;
    const int *ps, *pd;
    if (i < EH)                 { pair = 0; ps = hs0; pd = hd0; off = i; }
    else if (i < EH + ES)       { pair = 1; ps = ss0; pd = sd0; off = i - EH; }
    else if (i < 2 * EH + ES)   { pair = 2; ps = hs1; pd = hd1; off = i - EH - ES; }
    else                        { pair = 3; ps = ss1; pd = sd1; off = i - 2 * EH - ES; }
    int d = __ldg(pd + off);
    int pos = atomicAdd(&g_cur[pair * N_NODES + d], 1);
    g_eidx[eidx_base(pair) + pos] = __ldg(ps + off);
}

// ---------------- Hdelta = H - HBar (coalesced elementwise) ----------------
template <int LAYER>
__global__ void hdelta_kernel(const float* __restrict__ Hext, const float* __restrict__ hbar) {
    int i = blockIdx.x * blockDim.x + threadIdx.x;
    if (i >= N_NODES * D / 4) return;
    const float4* H4 = (LAYER == 0) ? (const float4*)Hext : (const float4*)g_H1;
    float4 a = __ldg(H4 + i);
    float4 b = __ldg((const float4*)hbar + i);
    ((float4*)g_Hd)[i] = make_float4(a.x - b.x, a.y - b.y, a.z - b.z, a.w - b.w);
}

// ---------------- fused gather aggregation (warp per dst node, MLP=4) ----------------
__device__ __forceinline__ void acc_add(float4& a, float4 v) {
    a.x += v.x; a.y += v.y; a.z += v.z; a.w += v.w;
}

template <int HPAIR, int DPAIR>
__global__ void agg_fused_kernel(const float* __restrict__ hbar) {
    int g = blockIdx.x * blockDim.x + threadIdx.x;
    int w = g >> 5, lane = g & 31;
    if (w >= N_NODES) return;
    const int* offH = g_off + HPAIR * (N_NODES + 1);
    const int* offD = g_off + DPAIR * (N_NODES + 1);
    const int* idxH = g_eidx + eidx_base(HPAIR);
    const int* idxD = g_eidx + eidx_base(DPAIR);
    int h0 = __ldg(offH + w), h1 = __ldg(offH + w + 1);
    int d0 = __ldg(offD + w), d1 = __ldg(offD + w + 1);

    // ---- hist: mean of hbar[src], 4-way unrolled for MLP ----
    float4 a0 = make_float4(0,0,0,0), a1 = a0, a2 = a0, a3 = a0;
    int e = h0;
    for (; e + 4 <= h1; e += 4) {
        int i0 = __ldg(idxH + e + 0), i1 = __ldg(idxH + e + 1);
        int i2 = __ldg(idxH + e + 2), i3 = __ldg(idxH + e + 3);
        float4 v0 = __ldg((const float4*)(hbar + (size_t)i0 * D) + lane);
        float4 v1 = __ldg((const float4*)(hbar + (size_t)i1 * D) + lane);
        float4 v2 = __ldg((const float4*)(hbar + (size_t)i2 * D) + lane);
        float4 v3 = __ldg((const float4*)(hbar + (size_t)i3 * D) + lane);
        acc_add(a0, v0); acc_add(a1, v1); acc_add(a2, v2); acc_add(a3, v3);
    }
    for (; e < h1; e++) {
        int s = __ldg(idxH + e);
        acc_add(a0, __ldg((const float4*)(hbar + (size_t)s * D) + lane));
    }
    acc_add(a0, a1); acc_add(a2, a3); acc_add(a0, a2);
    float invh = 1.f / fmaxf((float)(h1 - h0), 1.f);
    float4 o = make_float4(a0.x * invh, a0.y * invh, a0.z * invh, a0.w * invh);

    // ---- delta: mean of g_Hd[src], 4-way unrolled ----
    float4 b0 = make_float4(0,0,0,0), b1 = b0, b2 = b0, b3 = b0;
    e = d0;
    for (; e + 4 <= d1; e += 4) {
        int i0 = __ldg(idxD + e + 0), i1 = __ldg(idxD + e + 1);
        int i2 = __ldg(idxD + e + 2), i3 = __ldg(idxD + e + 3);
        float4 v0 = __ldg((const float4*)(g_Hd + (size_t)i0 * D) + lane);
        float4 v1 = __ldg((const float4*)(g_Hd + (size_t)i1 * D) + lane);
        float4 v2 = __ldg((const float4*)(g_Hd + (size_t)i2 * D) + lane);
        float4 v3 = __ldg((const float4*)(g_Hd + (size_t)i3 * D) + lane);
        acc_add(b0, v0); acc_add(b1, v1); acc_add(b2, v2); acc_add(b3, v3);
    }
    for (; e < d1; e++) {
        int s = __ldg(idxD + e);
        acc_add(b0, __ldg((const float4*)(g_Hd + (size_t)s * D) + lane));
    }
    acc_add(b0, b1); acc_add(b2, b3); acc_add(b0, b2);
    float invd = 1.f / fmaxf((float)(d1 - d0), 1.f);
    o.x += b0.x * invd; o.y += b0.y * invd;
    o.z += b0.z * invd; o.w += b0.w * invd;

    *(float4*)(g_neigh + (size_t)w * D + lane * 4) = o;
}

// ---------------- GEMM + bias + ReLU ----------------
// out[r][n] = relu(b[n] + sum_k z[r][k] W[n][k]),  z = [H_row | g_neigh_row]
// 256 threads, 16x16 thread grid over BM x BN tile (TM rows, TN cols each).
// Register double-buffered gmem loads; B fragments read pre-packed as ulonglong2.
template <int LAYER, int DOUT, int BM, int BN, int TM, int TN, int MAXB>
__global__ void __launch_bounds__(256, MAXB)
gemm_kernel(const float* __restrict__ Hext,
            const float* __restrict__ W,
            const float* __restrict__ bias,
            float* __restrict__ outext) {
    constexpr int BK = 32, K = 2 * D, NK = K / BK;
    constexpr int TNP = TN / 2;
    constexpr int NA = (BM * BK) / (256 * 4);   // float4 A loads per thread
    constexpr int NB = (BN * BK) / (256 * 4);   // float4 B loads per thread
    constexpr int APAD = BM + 4;
    constexpr int BPAD = BN + 4;

    const float* H = (LAYER == 0) ? Hext : g_H1;
    float* out     = (LAYER == 0) ? g_H1 : outext;

    __shared__ float As[BK][APAD];
    __shared__ float Bs[BK][BPAD];

    const int t    = threadIdx.x;
    const int row0 = blockIdx.x * BM;
    const int tx   = t & 15;
    const int ty   = t >> 4;

    float4 pa[NA], pb[NB];

    // ---- tile load into registers ----
    auto load_tile = [&](int kit) {
        const int k0 = kit * BK;
        const float* Asrc = (k0 < D) ? (H + k0) : (g_neigh + (k0 - D));
#pragma unroll
        for (int v = 0; v < NA; v++) {
            int id = v * 256 + t;
            int m  = id >> 3;
            int kq = id & 7;
            int r  = min(row0 + m, N_NODES - 1);
            pa[v] = __ldg((const float4*)(Asrc + (size_t)r * D) + kq);
        }
#pragma unroll
        for (int v = 0; v < NB; v++) {
            int id = v * 256 + t;
            int n  = id >> 3;
            int kq = id & 7;
            pb[v] = (n < DOUT) ? __ldg((const float4*)(W + n * K + k0) + kq)
                               : make_float4(0.f, 0.f, 0.f, 0.f);
        }
    };
    auto store_tile = [&]() {
#pragma unroll
        for (int v = 0; v < NA; v++) {
            int id = v * 256 + t;
            int m  = id >> 3;
            int kq = id & 7;
            int col = (((m >> 2) ^ (kq >> 1)) << 2) + (m & 3);
            As[(kq << 2) + 0][col] = pa[v].x;
            As[(kq << 2) + 1][col] = pa[v].y;
            As[(kq << 2) + 2][col] = pa[v].z;
            As[(kq << 2) + 3][col] = pa[v].w;
        }
#pragma unroll
        for (int v = 0; v < NB; v++) {
            int id = v * 256 + t;
            int n  = id >> 3;
            int kq = id & 7;
            int col = (((n >> 2) ^ (kq >> 1)) << 2) + (n & 3);
            Bs[(kq << 2) + 0][col] = pb[v].x;
            Bs[(kq << 2) + 1][col] = pb[v].y;
            Bs[(kq << 2) + 2][col] = pb[v].z;
            Bs[(kq << 2) + 3][col] = pb[v].w;
        }
    };

    ull acc2[TM][TNP];
#pragma unroll
    for (int i = 0; i < TM; i++)
#pragma unroll
        for (int p = 0; p < TNP; p++) acc2[i][p] = 0ULL;

    load_tile(0);

    for (int kit = 0; kit < NK; kit++) {
        store_tile();
        __syncthreads();
        if (kit + 1 < NK) load_tile(kit + 1);   // LDGs in flight during compute

#pragma unroll
        for (int kk = 0; kk < BK; kk++) {
            const int s = (kk >> 3) & 3;
            // A fragment: TM rows = TM/4 swizzled float4 groups
            ull ad[TM];
#pragma unroll
            for (int u = 0; u < TM / 4; u++) {
                int gA = ((TM / 4) * ty + u) ^ s;
                float4 a = *(const float4*)&As[kk][gA << 2];
                ad[4 * u + 0] = packf2(a.x, a.x);
                ad[4 * u + 1] = packf2(a.y, a.y);
                ad[4 * u + 2] = packf2(a.z, a.z);
                ad[4 * u + 3] = packf2(a.w, a.w);
            }
            // B fragment: read pre-packed pairs directly
            ull bp[TNP];
#pragma unroll
            for (int u = 0; u < TN / 4; u++) {
                int gB = (tx * (TN / 4) + u) ^ s;
                ulonglong2 bb = *(const ulonglong2*)&Bs[kk][gB << 2];
                bp[2 * u + 0] = bb.x;
                bp[2 * u + 1] = bb.y;
            }
#pragma unroll
            for (int i = 0; i < TM; i++)
#pragma unroll
                for (int p = 0; p < TNP; p++)
                    acc2[i][p] = fma2(ad[i], bp[p], acc2[i][p]);
        }
        __syncthreads();
    }

    // ---- epilogue ----
    float bn[TN];
#pragma unroll
    for (int j = 0; j < TN; j++) {
        int n = tx * TN + j;
        bn[j] = (n < DOUT) ? __ldg(bias + n) : 0.f;
    }
#pragma unroll
    for (int i = 0; i < TM; i++) {
        int r = row0 + ty * TM + i;
        if (r >= N_NODES) continue;
        float res[TN];
#pragma unroll
        for (int p = 0; p < TNP; p++) {
            float lo, hi;
            unpackf2(acc2[i][p], lo, hi);
            res[2 * p + 0] = fmaxf(lo + bn[2 * p + 0], 0.f);
            res[2 * p + 1] = fmaxf(hi + bn[2 * p + 1], 0.f);
        }
        if (DOUT == BN) {
#pragma unroll
            for (int u = 0; u < TN / 4; u++) {
                float4 o = make_float4(res[4 * u], res[4 * u + 1],
                                       res[4 * u + 2], res[4 * u + 3]);
                *(float4*)(out + (size_t)r * DOUT + tx * TN + 4 * u) = o;
            }
        } else {
#pragma unroll
            for (int j = 0; j < TN; j++) {
                int n = tx * TN + j;
                if (n < DOUT) out[(size_t)r * DOUT + n] = res[j];
            }
        }
    }
}

// ---------------- launch ----------------
extern "C" void kernel_launch(void* const* d_in, const int* in_sizes, int n_in,
                              void* d_out, int out_size) {
    const float* x     = (const float*)d_in[0];
    const float* hbar0 = (const float*)d_in[1];
    const float* hbar1 = (const float*)d_in[2];
    const float* W0    = (const float*)d_in[3];
    const float* b0    = (const float*)d_in[4];
    const float* W1    = (const float*)d_in[5];
    const float* b1    = (const float*)d_in[6];
    const int* hsrc0   = (const int*)d_in[7];
    const int* hdst0   = (const int*)d_in[8];
    const int* ssrc0   = (const int*)d_in[9];
    const int* sdst0   = (const int*)d_in[10];
    const int* hsrc1   = (const int*)d_in[11];
    const int* hdst1   = (const int*)d_in[12];
    const int* ssrc1   = (const int*)d_in[13];
    const int* sdst1   = (const int*)d_in[14];
    float* out = (float*)d_out;

    const int GE   = (E_TOT + 255) / 256;         // 5860
    const int GAGG = (N_NODES * 32 + 255) / 256;  // 6250
    const int GEL  = (N_NODES * D / 4 + 255) / 256;

    // ---- CSR build ----
    void* cnt_ptr = nullptr;
    cudaGetSymbolAddress(&cnt_ptr, g_cnt);
    cudaMemsetAsync(cnt_ptr, 0, sizeof(int) * 4 * N_NODES);
    count_all_kernel<<<GE, 256>>>(hdst0, sdst0, hdst1, sdst1);
    scan_kernel<<<4, 1024>>>();
    bucket_all_kernel<<<GE, 256>>>(hsrc0, hdst0, ssrc0, sdst0,
                                   hsrc1, hdst1, ssrc1, sdst1);

    // ---- layer 0 ----
    hdelta_kernel<0><<<GEL, 256>>>(x, hbar0);
    agg_fused_kernel<0, 1><<<GAGG, 256>>>(hbar0);
    gemm_kernel<0, 128, 128, 128, 8, 8, 2><<<(N_NODES + 127) / 128, 256>>>(x, W0, b0, nullptr);

    // ---- layer 1 ----
    hdelta_kernel<1><<<GEL, 256>>>(nullptr, hbar1);
    agg_fused_kernel<2, 3><<<GAGG, 256>>>(hbar1);
    gemm_kernel<1, NCLS, 64, 64, 4, 4, 3><<<(N_NODES + 63) / 64, 256>>>(nullptr, W1, b1, out);
}